// round 14
// baseline (speedup 1.0000x reference)
#include <cuda_runtime.h>
#include <cuda_fp16.h>
#include <cstdint>
#include <cstddef>

#define NT 256
#define XP 72   // halves per smem matrix row (144B: conflict-free ldmatrix, 16B-aligned)

namespace {
constexpr int Bb = 2, Ss = 512, Ll = 384, CMc = 64;

struct __align__(16) SMem {
    __half x[512 * XP];      // post-LN x fp16, row-major [s][c]     73,728B
    __half wvB[64 * XP];     // wv^T tile: row n, col k               9,216B
    union {
        float LG[8 * 512];   // logits->attn [h][s]                  16,384B
        struct { __half wgB[64 * XP]; __half woB[64 * XP]; } go;  // 18,432B
    } u;
    float maskS[512];
    float pbuf[8 * 64];      // qin partials; og partials
    __half a_h[8 * XP];      // a fp16 [h][j]
    float qin[64];
    float qsm[64];
    float og[64];
    float bgS[64];
    float red[8];
};
}  // namespace

__device__ __forceinline__ uint32_t s2u(const void* p) {
    uint32_t a;
    asm("{ .reg .u64 t; cvta.to.shared.u64 t, %1; cvt.u32.u64 %0, t; }" : "=r"(a) : "l"(p));
    return a;
}
__device__ __forceinline__ void ldmA(uint32_t* a, uint32_t addr) {
    asm volatile("ldmatrix.sync.aligned.m8n8.x4.shared.b16 {%0,%1,%2,%3}, [%4];"
                 : "=r"(a[0]), "=r"(a[1]), "=r"(a[2]), "=r"(a[3]) : "r"(addr));
}
__device__ __forceinline__ void mma16816(float* d, const uint32_t* a, const uint32_t* b) {
    asm volatile(
        "mma.sync.aligned.m16n8k16.row.col.f32.f16.f16.f32 "
        "{%0,%1,%2,%3}, {%4,%5,%6,%7}, {%8,%9}, {%0,%1,%2,%3};"
        : "+f"(d[0]), "+f"(d[1]), "+f"(d[2]), "+f"(d[3])
        : "r"(a[0]), "r"(a[1]), "r"(a[2]), "r"(a[3]), "r"(b[0]), "r"(b[1]));
}
__device__ __forceinline__ float sgm(float x) { return 1.0f / (1.0f + __expf(-x)); }
__device__ __forceinline__ uint32_t packh2(float a, float b) {
    __half2 h = __floats2half2_rn(a, b);
    return *reinterpret_cast<uint32_t*>(&h);
}

__global__ void __launch_bounds__(NT, 2)
msa_col_global_attn(const float* __restrict__ m, const float* __restrict__ msa_mask,
                    const float* __restrict__ lnw, const float* __restrict__ lnb,
                    const float* __restrict__ wq, const float* __restrict__ wk,
                    const float* __restrict__ wv, const float* __restrict__ wg,
                    const float* __restrict__ bg, const float* __restrict__ wo,
                    const float* __restrict__ bo, float* __restrict__ out)
{
    extern __shared__ __align__(16) char smraw[];
    SMem& sm = *reinterpret_cast<SMem*>(smraw);
    const int tid = threadIdx.x;
    const int w = tid >> 5, lane = tid & 31;
    const int b = blockIdx.x / Ll, l = blockIdx.x - b * Ll;
    const size_t rowStride = (size_t)Ll * CMc;
    const float* mBase = m + ((size_t)b * Ss * Ll + l) * CMc;
    float* oBase = out + ((size_t)b * Ss * Ll + l) * CMc;

    // ---- Phase 0: mask, wv tile, bg, LayerNorm (warp owns 64 rows) + qin fold ----
    const int row0 = w * 64 + lane, row1 = row0 + 32;
    float mkA = msa_mask[((size_t)b * Ss + row0) * Ll + l];
    float mkB = msa_mask[((size_t)b * Ss + row1) * Ll + l];
    sm.maskS[row0] = mkA;
    sm.maskS[row1] = mkB;
    {
        float ms = mkA + mkB;
#pragma unroll
        for (int o = 16; o; o >>= 1) ms += __shfl_xor_sync(0xffffffffu, ms, o);
        if (lane == 0) sm.red[w] = ms;
    }
    for (int idx = tid; idx < 4096; idx += NT) {
        int n = idx & 63, k = idx >> 6;
        sm.wvB[n * XP + k] = __float2half(__ldg(&wv[k * 64 + n]));
    }
    if (tid < 64) sm.bgS[tid] = __ldg(&bg[tid]);
    {
        const float lwA = lnw[lane], lwB = lnw[lane + 32];
        const float lbA = lnb[lane], lbB = lnb[lane + 32];
        float qA = 0.f, qB = 0.f;
#pragma unroll 1
        for (int rb = 0; rb < 8; rb++) {
            float a0[8], a1[8];
#pragma unroll
            for (int r = 0; r < 8; r++) {
                int s = w * 64 + rb * 8 + r;
                const float* mp = mBase + (size_t)s * rowStride;
                a0[r] = mp[lane];
                a1[r] = mp[lane + 32];
            }
            float msel = (rb < 4) ? mkA : mkB;
            int bidx = (rb < 4) ? rb * 8 : rb * 8 - 32;
#pragma unroll
            for (int r = 0; r < 8; r++) {
                int s = w * 64 + rb * 8 + r;
                float su = a0[r] + a1[r];
                float sq = fmaf(a0[r], a0[r], a1[r] * a1[r]);
#pragma unroll
                for (int o = 16; o; o >>= 1) {
                    su += __shfl_xor_sync(0xffffffffu, su, o);
                    sq += __shfl_xor_sync(0xffffffffu, sq, o);
                }
                float mu = su * (1.0f / 64.0f);
                float var = sq * (1.0f / 64.0f) - mu * mu;
                float rs = rsqrtf(var + 1e-5f);
                float vA = (a0[r] - mu) * rs * lwA + lbA;
                float vB = (a1[r] - mu) * rs * lwB + lbB;
                sm.x[s * XP + lane]      = __float2half(vA);
                sm.x[s * XP + lane + 32] = __float2half(vB);
                float mks = __shfl_sync(0xffffffffu, msel, bidx + r);
                qA = fmaf(vA, mks, qA);
                qB = fmaf(vB, mks, qB);
            }
        }
        sm.pbuf[w * 64 + lane]      = qA;
        sm.pbuf[w * 64 + lane + 32] = qB;
    }
    __syncthreads();  // S1

    // ---- warp-0 chain: qin -> q -> a_h (fp16 [h][j]) ----
    if (w == 0) {
        float d = 0.f;
#pragma unroll
        for (int i = 0; i < 8; i++) d += sm.red[i];
        float inv = 1.0f / fmaxf(d, 1.0f);
        float q0 = 0.f, q1 = 0.f;
#pragma unroll
        for (int i = 0; i < 8; i++) {
            q0 += sm.pbuf[i * 64 + lane];
            q1 += sm.pbuf[i * 64 + lane + 32];
        }
        sm.qin[lane] = q0 * inv;
        sm.qin[lane + 32] = q1 * inv;
        __syncwarp();
        float a0 = 0.f, a1 = 0.f;
#pragma unroll
        for (int j = 0; j < 64; j++) {
            float qj = sm.qin[j];
            a0 = fmaf(qj, __ldg(&wq[j * 64 + lane]), a0);
            a1 = fmaf(qj, __ldg(&wq[j * 64 + lane + 32]), a1);
        }
        sm.qsm[lane] = a0;
        sm.qsm[lane + 32] = a1;
        __syncwarp();
#pragma unroll 1
        for (int t = 0; t < 16; t++) {
            int idx = t * 32 + lane;
            int j = idx >> 3, h = idx & 7;
            float acc = 0.f;
#pragma unroll
            for (int c = 0; c < 8; c++)
                acc = fmaf(sm.qsm[h * 8 + c], __ldg(&wk[j * 64 + h * 8 + c]), acc);
            sm.a_h[h * XP + j] = __float2half(acc * 0.35355339059327373f);  // 1/sqrt(C)
        }
    }
    __syncthreads();  // S2

    // ---- Logits via HMMA: warp w rows w*64..+63 ----
    {
        uint32_t Bf[4][2];
#pragma unroll
        for (int kt = 0; kt < 4; kt++) {
            int row = lane >> 2;
            int col = kt * 16 + (lane & 3) * 2;
            Bf[kt][0] = *reinterpret_cast<const uint32_t*>(&sm.a_h[row * XP + col]);
            Bf[kt][1] = *reinterpret_cast<const uint32_t*>(&sm.a_h[row * XP + col + 8]);
        }
#pragma unroll
        for (int mt = 0; mt < 4; mt++) {
            int s0 = w * 64 + mt * 16;
            uint32_t A[4][4];
#pragma unroll
            for (int kt = 0; kt < 4; kt++)
                ldmA(A[kt], s2u(&sm.x[(s0 + (lane & 15)) * XP + kt * 16 + ((lane >> 4) << 3)]));
            float acc[4] = {0, 0, 0, 0};
#pragma unroll
            for (int kt = 0; kt < 4; kt++) mma16816(acc, A[kt], Bf[kt]);
            int r = s0 + (lane >> 2);
            int h0 = (lane & 3) * 2;
            float mA = sm.maskS[r], mB = sm.maskS[r + 8];
            sm.u.LG[h0 * 512 + r]           = (mA != 0.0f) ? acc[0] : -1e9f;
            sm.u.LG[(h0 + 1) * 512 + r]     = (mA != 0.0f) ? acc[1] : -1e9f;
            sm.u.LG[h0 * 512 + r + 8]       = (mB != 0.0f) ? acc[2] : -1e9f;
            sm.u.LG[(h0 + 1) * 512 + r + 8] = (mB != 0.0f) ? acc[3] : -1e9f;
        }
    }
    __syncthreads();  // S3

    // ---- softmax, warp w owns head w ----
    {
        float vals[16];
        float lm = -3.4e38f;
#pragma unroll
        for (int k = 0; k < 16; k++) {
            vals[k] = sm.u.LG[w * 512 + lane + k * 32];
            lm = fmaxf(lm, vals[k]);
        }
#pragma unroll
        for (int o = 16; o; o >>= 1) lm = fmaxf(lm, __shfl_xor_sync(0xffffffffu, lm, o));
        float ls = 0.f;
#pragma unroll
        for (int k = 0; k < 16; k++) {
            vals[k] = __expf(vals[k] - lm);
            ls += vals[k];
        }
#pragma unroll
        for (int o = 16; o; o >>= 1) ls += __shfl_xor_sync(0xffffffffu, ls, o);
        float inv = 1.0f / ls;
#pragma unroll
        for (int k = 0; k < 16; k++) sm.u.LG[w * 512 + lane + k * 32] = vals[k] * inv;
    }
    __syncthreads();  // S4: attn ready

    // ---- Fused Pass V + og: warp w rows w*64..+63, all 64 cols ----
    {
        float ogp[16];
#pragma unroll
        for (int k = 0; k < 16; k++) ogp[k] = 0.f;
        const int k0 = (lane & 3) * 2;
#pragma unroll 1
        for (int mt = 0; mt < 4; mt++) {
            int s0 = w * 64 + mt * 16;
            uint32_t A[4][4];
#pragma unroll
            for (int kt = 0; kt < 4; kt++)
                ldmA(A[kt], s2u(&sm.x[(s0 + (lane & 15)) * XP + kt * 16 + ((lane >> 4) << 3)]));
            int r = s0 + (lane >> 2);
#pragma unroll
            for (int nt = 0; nt < 8; nt++) {
                uint32_t Bv[4][2];
#pragma unroll
                for (int kt = 0; kt < 4; kt++) {
                    int row = nt * 8 + (lane >> 2);
                    int col = kt * 16 + k0;
                    Bv[kt][0] = *reinterpret_cast<const uint32_t*>(&sm.wvB[row * XP + col]);
                    Bv[kt][1] = *reinterpret_cast<const uint32_t*>(&sm.wvB[row * XP + col + 8]);
                }
                float acc[4] = {0, 0, 0, 0};
#pragma unroll
                for (int kt = 0; kt < 4; kt++) mma16816(acc, A[kt], Bv[kt]);
                float aA = sm.u.LG[nt * 512 + r];
                float aB = sm.u.LG[nt * 512 + r + 8];
                ogp[2 * nt]     = fmaf(aA, acc[0], fmaf(aB, acc[2], ogp[2 * nt]));
                ogp[2 * nt + 1] = fmaf(aA, acc[1], fmaf(aB, acc[3], ogp[2 * nt + 1]));
            }
        }
#pragma unroll
        for (int k = 0; k < 16; k++) {
            ogp[k] += __shfl_xor_sync(0xffffffffu, ogp[k], 4);
            ogp[k] += __shfl_xor_sync(0xffffffffu, ogp[k], 8);
            ogp[k] += __shfl_xor_sync(0xffffffffu, ogp[k], 16);
        }
        if (lane < 4) {
#pragma unroll
            for (int nt = 0; nt < 8; nt++) {
                sm.pbuf[w * 64 + nt * 8 + k0]     = ogp[2 * nt];
                sm.pbuf[w * 64 + nt * 8 + k0 + 1] = ogp[2 * nt + 1];
            }
        }
    }
    __syncthreads();  // S5: LG dead from here; og partials ready

    // ---- og reduce + stage wg/wo tiles into the union ----
    if (tid < 64) {
        float acc = 0.f;
#pragma unroll
        for (int w2 = 0; w2 < 8; w2++) acc += sm.pbuf[w2 * 64 + tid];
        sm.og[tid] = acc;
    }
    for (int idx = tid; idx < 4096; idx += NT) {
        int n = idx & 63, k = idx >> 6;
        sm.u.go.wgB[n * XP + k] = __float2half(__ldg(&wg[k * 64 + n]));
        sm.u.go.woB[n * XP + k] = __float2half(__ldg(&wo[k * 64 + n]));
    }
    __syncthreads();  // S6: og + wg/wo tiles ready

    // ---- Fused G+O: warp w rows w*64..+63 (transient per-nt D-frags, low regs) ----
    {
        const int k0 = (lane & 3) * 2;
#pragma unroll 1
        for (int mt2 = 0; mt2 < 4; mt2++) {
            int s0 = w * 64 + mt2 * 16;
            uint32_t Ax[4][4];
#pragma unroll
            for (int kt = 0; kt < 4; kt++)
                ldmA(Ax[kt], s2u(&sm.x[(s0 + (lane & 15)) * XP + kt * 16 + ((lane >> 4) << 3)]));
            // GEMM1 + epilogue per nt: acc transient, pack straight into Ap
            uint32_t Ap[4][4];
#pragma unroll
            for (int nt = 0; nt < 8; nt++) {
                uint32_t Bg[4][2];
#pragma unroll
                for (int kt = 0; kt < 4; kt++) {
                    int row = nt * 8 + (lane >> 2);
                    int col = kt * 16 + k0;
                    Bg[kt][0] = *reinterpret_cast<const uint32_t*>(&sm.u.go.wgB[row * XP + col]);
                    Bg[kt][1] = *reinterpret_cast<const uint32_t*>(&sm.u.go.wgB[row * XP + col + 8]);
                }
                float acc[4] = {0, 0, 0, 0};
#pragma unroll
                for (int kt = 0; kt < 4; kt++) mma16816(acc, Ax[kt], Bg[kt]);
                int c = nt * 8 + k0;
                float ogv0 = sm.og[c], ogv1 = sm.og[c + 1];
                float bg0 = sm.bgS[c], bg1 = sm.bgS[c + 1];
                float t0 = ogv0 * sgm(acc[0] + bg0);
                float t1 = ogv1 * sgm(acc[1] + bg1);
                float t2 = ogv0 * sgm(acc[2] + bg0);
                float t3 = ogv1 * sgm(acc[3] + bg1);
                int kt2 = nt >> 1, hi = nt & 1;
                Ap[kt2][hi * 2]     = packh2(t0, t1);
                Ap[kt2][hi * 2 + 1] = packh2(t2, t3);
            }
            // GEMM2: out = (t @ wo + bo) * mask -> global
            int r = s0 + (lane >> 2);
            float mA = sm.maskS[r], mB = sm.maskS[r + 8];
#pragma unroll
            for (int nt2 = 0; nt2 < 8; nt2++) {
                uint32_t Bo[4][2];
#pragma unroll
                for (int kt = 0; kt < 4; kt++) {
                    int row = nt2 * 8 + (lane >> 2);
                    int col = kt * 16 + k0;
                    Bo[kt][0] = *reinterpret_cast<const uint32_t*>(&sm.u.go.woB[row * XP + col]);
                    Bo[kt][1] = *reinterpret_cast<const uint32_t*>(&sm.u.go.woB[row * XP + col + 8]);
                }
                float acc2[4] = {0, 0, 0, 0};
#pragma unroll
                for (int kt = 0; kt < 4; kt++) mma16816(acc2, Ap[kt], Bo[kt]);
                int c = nt2 * 8 + k0;
                float bo0 = __ldg(&bo[c]), bo1 = __ldg(&bo[c + 1]);
                *reinterpret_cast<float2*>(oBase + (size_t)r * rowStride + c) =
                    make_float2((acc2[0] + bo0) * mA, (acc2[1] + bo1) * mA);
                *reinterpret_cast<float2*>(oBase + (size_t)(r + 8) * rowStride + c) =
                    make_float2((acc2[2] + bo0) * mB, (acc2[3] + bo1) * mB);
            }
        }
    }
}

extern "C" void kernel_launch(void* const* d_in, const int* in_sizes, int n_in,
                              void* d_out, int out_size)
{
    (void)in_sizes; (void)n_in; (void)out_size;
    const float* m    = (const float*)d_in[0];
    const float* mask = (const float*)d_in[1];
    const float* lnw  = (const float*)d_in[2];
    const float* lnb  = (const float*)d_in[3];
    const float* wq   = (const float*)d_in[4];
    const float* wk   = (const float*)d_in[5];
    const float* wv   = (const float*)d_in[6];
    const float* wg   = (const float*)d_in[7];
    const float* bg   = (const float*)d_in[8];
    const float* wo   = (const float*)d_in[9];
    const float* bo   = (const float*)d_in[10];
    float* out = (float*)d_out;

    cudaFuncSetAttribute(msa_col_global_attn,
                         cudaFuncAttributeMaxDynamicSharedMemorySize,
                         (int)sizeof(SMem));
    msa_col_global_attn<<<Bb * Ll, NT, sizeof(SMem)>>>(
        m, mask, lnw, lnb, wq, wk, wv, wg, bg, wo, bo, out);
}